// round 9
// baseline (speedup 1.0000x reference)
#include <cuda_runtime.h>
#include <math.h>
#include <stdint.h>

#define BB 4
#define NN 100000
#define KK 16
#define NPAIR (NN / 2)
#define EPSF 1e-6f
#define W_CE 2.0f
#define W_DICE 0.1f

#define GX 111                 // blocks per batch (444 total = 3/SM)
#define NBLK (GX * BB)
#define NWPB 8                 // warps per block
#define NWARP (GX * NWPB)      // 888 warps per batch
#define UD 2                   // macro-iteration depth (pairs per group)
#define MITER ((NPAIR + UD * NWARP - 1) / (UD * NWARP))   // 29
#define ENT 544                // padded slot; real: 256 D | 256 INTER | 16 S1M
#define NE_REAL 528
#define NE_TOT (BB * NE_REAL)  // 2112

struct Part { float e[ENT]; };
__device__ Part g_part[NBLK];
__device__ int g_count;        // self-resetting

// ---------------------------------------------------------------------------
__device__ __forceinline__ unsigned long long pack_dup(float x) {
    unsigned long long r;
    unsigned int u = __float_as_uint(x);
    asm("mov.b64 %0, {%1, %1};" : "=l"(r) : "r"(u));
    return r;
}
__device__ __forceinline__ void fma2(unsigned long long& acc,
                                     unsigned long long a,
                                     unsigned long long b) {
    asm("fma.rn.f32x2 %0, %1, %2, %0;" : "+l"(acc) : "l"(a), "l"(b));
}
__device__ __forceinline__ float lo32(unsigned long long x) {
    return __uint_as_float((unsigned int)(x & 0xffffffffULL));
}
__device__ __forceinline__ float hi32(unsigned long long x) {
    return __uint_as_float((unsigned int)(x >> 32));
}

// ---------------------------------------------------------------------------
__global__ void __launch_bounds__(256, 3) fused_kernel(
    const float* __restrict__ mask,
    const float* __restrict__ gt,
    const float* __restrict__ valid,
    float* __restrict__ out) {
    __shared__ float pti[NWPB][ENT];
    __shared__ float v1m[NWPB][32];
    __shared__ float facc[NE_TOT];
    __shared__ float cost[BB][KK][KK];
    __shared__ float mS1M[BB][KK], mSUMM[BB][KK], mSUMG[BB][KK], mV[BB];
    __shared__ int colmap[BB][KK];
    __shared__ float rce[BB * KK], rdice[BB * KK];
    __shared__ int is_last;

    const int b = blockIdx.y;
    const int bx = blockIdx.x;
    const int t = threadIdx.x;
    const int lane = t & 31;
    const int w = t >> 5;
    const int i = lane & 15;   // cost-row index owned by this lane
    const int jh = lane >> 4;  // j-half owned; also row-of-pair
    const unsigned FULL = 0xffffffffu;
    const int gwarp = bx * NWPB + w;

    const float* mask_b = mask + (size_t)b * NN * KK;
    const float* gt_b = gt + (size_t)b * NN * KK;
    const float* val_b = valid + (size_t)b * NN;

    // lane-relative gt offsets (in floats)
    const int oo0 = jh * 24;
    const int oo1 = jh * 24 + 4;
    const int ox0 = 16 - 8 * jh;
    const int ox1 = 20 - 8 * jh;
    const int om = lane;

    unsigned long long aD[4], aI[4];
#pragma unroll
    for (int k = 0; k < 4; k++) { aD[k] = 0ull; aI[k] = 0ull; }
    float s1m = 0.0f;   // accumulates +v*log2(1-m); negated at writeback

    // ---- main loop: UD-deep flat load phase, then compute phase ----
#pragma unroll 1
    for (int mi = 0; mi < MITER; mi++) {
        const int pr0 = gwarp + mi * (UD * NWARP);

        float mv[UD];
        float va[UD], vb[UD];
        unsigned long long go0x[UD], go0y[UD], go1x[UD], go1y[UD];
        unsigned long long gx0x[UD], gx0y[UD], gx1x[UD], gx1y[UD];

        // LOAD PHASE: 12 independent LDGs, front-batched
#pragma unroll
        for (int k = 0; k < UD; k++) {
            const int pr = pr0 + k * NWARP;
            const int ok = (pr < NPAIR);
            const size_t off = ok ? (size_t)pr * 32 : 0;
            const size_t voff = ok ? (size_t)pr * 2 : 0;
            const float* gb = gt_b + off;
            mv[k] = mask_b[off + om];
            float2 v2 = *(const float2*)(val_b + voff);
            va[k] = ok ? v2.x : 0.0f;
            vb[k] = ok ? v2.y : 0.0f;
            ulonglong2 u;
            u = *(const ulonglong2*)(gb + oo0); go0x[k] = u.x; go0y[k] = u.y;
            u = *(const ulonglong2*)(gb + oo1); go1x[k] = u.x; go1y[k] = u.y;
            u = *(const ulonglong2*)(gb + ox0); gx0x[k] = u.x; gx0y[k] = u.y;
            u = *(const ulonglong2*)(gb + ox1); gx1x[k] = u.x; gx1y[k] = u.y;
        }

        // COMPUTE PHASE
#pragma unroll
        for (int k = 0; k < UD; k++) {
            float vown = jh ? vb[k] : va[k];
            float l1 = __log2f(mv[k]);
            float l2 = __log2f(1.0f - mv[k]);
            float down = vown * (l2 - l1);   // D weight (log2 space)
            float rown = vown * mv[k];       // INTER weight
            s1m = fmaf(vown, l2, s1m);

            float doth = __shfl_xor_sync(FULL, down, 16);
            float roth = __shfl_xor_sync(FULL, rown, 16);

            unsigned long long Dw = pack_dup(down), Rw = pack_dup(rown);
            unsigned long long Dx = pack_dup(doth), Rx = pack_dup(roth);

            fma2(aD[0], Dw, go0x[k]); fma2(aD[1], Dw, go0y[k]);
            fma2(aD[2], Dw, go1x[k]); fma2(aD[3], Dw, go1y[k]);
            fma2(aI[0], Rw, go0x[k]); fma2(aI[1], Rw, go0y[k]);
            fma2(aI[2], Rw, go1x[k]); fma2(aI[3], Rw, go1y[k]);

            fma2(aD[0], Dx, gx0x[k]); fma2(aD[1], Dx, gx0y[k]);
            fma2(aD[2], Dx, gx1x[k]); fma2(aD[3], Dx, gx1y[k]);
            fma2(aI[0], Rx, gx0x[k]); fma2(aI[1], Rx, gx0y[k]);
            fma2(aI[2], Rx, gx1x[k]); fma2(aI[3], Rx, gx1y[k]);
        }
    }

    // ---- per-warp -> shared ----
    v1m[w][lane] = s1m;
    {
        const int basej = i * 16 + jh * 8;
#pragma unroll
        for (int k = 0; k < 4; k++) {
            pti[w][basej + 2 * k] = lo32(aD[k]);
            pti[w][basej + 2 * k + 1] = hi32(aD[k]);
            pti[w][256 + basej + 2 * k] = lo32(aI[k]);
            pti[w][256 + basej + 2 * k + 1] = hi32(aI[k]);
        }
    }
    __syncthreads();

    // ---- block reduce -> deterministic per-block partial slot ----
    Part* gp = &g_part[b * GX + bx];
#pragma unroll
    for (int e0 = 0; e0 < 512; e0 += 256) {
        int e = e0 + t;
        float sum = 0.0f;
#pragma unroll
        for (int ww = 0; ww < NWPB; ww++) sum += pti[ww][e];
        gp->e[e] = sum;
    }
    if (t < 16) {
        float sum = 0.0f;
#pragma unroll
        for (int ww = 0; ww < NWPB; ww++) sum += v1m[ww][t] + v1m[ww][t + 16];
        gp->e[512 + t] = -sum;   // S1M = -sum(v*log2(1-m))
    }

    __threadfence();
    __syncthreads();
    if (t == 0) {
        int old = atomicAdd(&g_count, 1);
        is_last = (old == NBLK - 1);
    }
    __syncthreads();
    if (!is_last) return;

    if (t == 0) g_count = 0;

    // ---- final reduce: 9 entries per thread, jammed for MLP ----
    {
        float sacc[9];
        const float* bas[9];
        int ok[9];
#pragma unroll
        for (int k = 0; k < 9; k++) {
            int q = t + k * 256;
            ok[k] = (q < NE_TOT);
            sacc[k] = 0.0f;
            if (ok[k]) {
                int bb2 = q / NE_REAL;
                int e = q - bb2 * NE_REAL;
                bas[k] = &g_part[bb2 * GX].e[e];
            } else {
                bas[k] = &g_part[0].e[0];
            }
        }
        for (int gx = 0; gx < GX; gx++) {
#pragma unroll
            for (int k = 0; k < 9; k++)
                if (ok[k]) sacc[k] += bas[k][(size_t)gx * ENT];
        }
#pragma unroll
        for (int k = 0; k < 9; k++) {
            int q = t + k * 256;
            if (ok[k]) facc[q] = sacc[k];
        }
    }
    __syncthreads();

    // ---- marginals from INTER (+ direct S1M) ----
    if (t < BB * KK) {
        int bb2 = t / KK, q = t % KK;
        const float* F = facc + bb2 * NE_REAL;
        float summ = 0.0f, sumg = 0.0f;
#pragma unroll
        for (int x = 0; x < KK; x++) {
            summ += F[256 + q * 16 + x];   // row sum of INTER
            sumg += F[256 + x * 16 + q];   // col sum of INTER
        }
        mS1M[bb2][q] = F[512 + q];
        mSUMM[bb2][q] = summ;
        mSUMG[bb2][q] = sumg;
    }
    __syncthreads();
    if (t < BB) {
        float v = 0.0f;
#pragma unroll
        for (int x = 0; x < KK; x++) v += mSUMG[t][x];
        mV[t] = v;
    }
    __syncthreads();

    // ---- cost matrices ----
    const float LN2 = 0.69314718055994530942f;
    for (int idx = t; idx < BB * 256; idx += 256) {
        int bb2 = idx >> 8;
        int r = idx & 255;
        int ii = r >> 4, jj = r & 15;
        const float* F = facc + bb2 * NE_REAL;
        float denom = fmaxf(mV[bb2], 1.0f);
        float ce = LN2 * (F[ii * 16 + jj] + mS1M[bb2][ii]) / denom;
        float dice = 1.0f - 2.0f * F[256 + ii * 16 + jj] /
                                (mSUMM[bb2][ii] + mSUMG[bb2][jj] + EPSF);
        cost[bb2][ii][jj] = W_CE * ce + W_DICE * dice;
    }
    __syncthreads();

    // ---- warp-parallel Hungarian (JV), one warp per batch ----
    if (w < BB) {
        const int bb2 = w;
        float ur = 0.0f;
        float vv = 0.0f;
        int pcol = 0;

        for (int ii = 1; ii <= KK; ii++) {
            if (lane == 0) pcol = ii;
            float minv = 1e30f;
            int way = 0;
            int used = 0;
            int rowcov = 0;
            int j0 = 0;

            while (true) {
                if (lane == j0) used = 1;
                int i0 = __shfl_sync(FULL, pcol, j0);
                if (lane == i0) rowcov = 1;
                float u_i0 = __shfl_sync(FULL, ur, i0);

                int active = (lane >= 1 && lane <= KK && !used);
                if (active) {
                    float c = cost[bb2][i0 - 1][lane - 1];
                    float cur = c - u_i0 - vv;
                    if (cur < minv) { minv = cur; way = j0; }
                }
                float val = active ? minv : 1e30f;
                float red = val;
#pragma unroll
                for (int off = 16; off; off >>= 1)
                    red = fminf(red, __shfl_xor_sync(FULL, red, off));
                unsigned bal = __ballot_sync(FULL, val == red);
                int j1 = __ffs(bal) - 1;
                float delta = red;

                if (rowcov) ur += delta;
                if (used) vv -= delta;
                else if (lane >= 1 && lane <= KK) minv -= delta;

                j0 = j1;
                int pj = __shfl_sync(FULL, pcol, j0);
                if (pj == 0) break;
            }
            while (j0 != 0) {
                int j1 = __shfl_sync(FULL, way, j0);
                int pv = __shfl_sync(FULL, pcol, j1);
                if (lane == j0) pcol = pv;
                j0 = j1;
            }
        }
        if (lane >= 1 && lane <= KK) colmap[bb2][pcol - 1] = lane - 1;
    }
    __syncthreads();

    // ---- loss ----
    if (t < BB * KK) {
        int bb2 = t / KK, ii = t % KK;
        int jj = colmap[bb2][ii];
        const float* F = facc + bb2 * NE_REAL;
        rce[t] = LN2 * (F[ii * 16 + jj] + mS1M[bb2][ii]);
        rdice[t] = 1.0f - 2.0f * F[256 + ii * 16 + jj] /
                              (mSUMM[bb2][ii] + mSUMG[bb2][jj] + EPSF);
    }
    __syncthreads();

    if (t == 0) {
        float cs = 0.0f, ds = 0.0f, vt = 0.0f;
        for (int x = 0; x < BB * KK; x++) { cs += rce[x]; ds += rdice[x]; }
        for (int bb2 = 0; bb2 < BB; bb2++) vt += mV[bb2];
        float l_ce = cs / (fmaxf(vt, 1.0f) * (float)KK);
        float l_dice = ds / (float)(BB * KK);
        out[0] = W_CE * l_ce + W_DICE * l_dice;
    }
}

// ---------------------------------------------------------------------------
extern "C" void kernel_launch(void* const* d_in, const int* in_sizes, int n_in,
                              void* d_out, int out_size) {
    const float* mask = (const float*)d_in[0];
    const float* gt = (const float*)d_in[1];
    const float* valid = (const float*)d_in[2];
    float* out = (float*)d_out;

    dim3 grid(GX, BB);
    fused_kernel<<<grid, 256>>>(mask, gt, valid, out);
}

// round 10
// speedup vs baseline: 1.1576x; 1.1576x over previous
#include <cuda_runtime.h>
#include <math.h>
#include <stdint.h>

#define BB 4
#define NN 100000
#define KK 16
#define EPSF 1e-6f
#define W_CE 2.0f
#define W_DICE 0.1f

#define GX 111                 // blocks per batch (444 total = 3/SM)
#define NBLK (GX * BB)
#define NWPB 8                 // warps per block
#define TROWS 64               // rows per tile (8 chunks of K=8)
#define NTILES ((NN + TROWS - 1) / TROWS)   // 1563; tail tile = 32 rows
#define STAGES 4
#define ENT 544                // padded slot; real: 256 D | 256 INTER | 16 S1M
#define NE_REAL 528
#define NE_TOT (BB * NE_REAL)  // 2112

struct Part { float e[ENT]; };
__device__ Part g_part[NBLK];
__device__ int g_count;        // self-resetting

// ---------------------------------------------------------------------------
struct __align__(16) Stg {
    float m[STAGES][TROWS * KK];   // 4KB per stage
    float g[STAGES][TROWS * KK];   // 4KB per stage
    float v[STAGES][TROWS];        // 256B per stage
};
struct __align__(16) Epi {
    float pti[NWPB][ENT];          // 17.4KB
    float facc[NE_TOT];            // 8.4KB
};
union ShU { Stg stg; Epi epi; };   // 33KB / 25.8KB

// ---------------------------------------------------------------------------
__device__ __forceinline__ uint32_t to_tf32(float x) {
    uint32_t r;
    asm("cvt.rna.tf32.f32 %0, %1;" : "=r"(r) : "f"(x));
    return r;
}
__device__ __forceinline__ void mma_tf32(float& d0, float& d1, float& d2,
                                         float& d3, uint32_t a0, uint32_t a1,
                                         uint32_t a2, uint32_t a3, uint32_t b0,
                                         uint32_t b1) {
    asm("mma.sync.aligned.m16n8k8.row.col.f32.tf32.tf32.f32 "
        "{%0,%1,%2,%3},{%4,%5,%6,%7},{%8,%9},{%0,%1,%2,%3};"
        : "+f"(d0), "+f"(d1), "+f"(d2), "+f"(d3)
        : "r"(a0), "r"(a1), "r"(a2), "r"(a3), "r"(b0), "r"(b1));
}
__device__ __forceinline__ void mbar_init(uint32_t mbar, uint32_t cnt) {
    asm volatile("mbarrier.init.shared.b64 [%0], %1;" :: "r"(mbar), "r"(cnt)
                 : "memory");
}
__device__ __forceinline__ void mbar_expect_tx(uint32_t mbar, uint32_t bytes) {
    asm volatile("mbarrier.arrive.expect_tx.shared.b64 _, [%0], %1;"
                 :: "r"(mbar), "r"(bytes) : "memory");
}
__device__ __forceinline__ void bulk_g2s(uint32_t dst, const void* src,
                                         uint32_t bytes, uint32_t mbar) {
    asm volatile(
        "cp.async.bulk.shared::cta.global.mbarrier::complete_tx::bytes "
        "[%0], [%1], %2, [%3];"
        :: "r"(dst), "l"(src), "r"(bytes), "r"(mbar) : "memory");
}
__device__ __forceinline__ void mbar_wait(uint32_t mbar, uint32_t phase) {
    uint32_t done;
    asm volatile(
        "{\n\t.reg .pred p;\n\t"
        "mbarrier.try_wait.parity.acquire.cta.shared::cta.b64 p, [%1], %2;\n\t"
        "selp.b32 %0, 1, 0, p;\n\t}"
        : "=r"(done) : "r"(mbar), "r"(phase) : "memory");
    if (!done) {
        asm volatile(
            "{\n\t.reg .pred P1;\n\t"
            "WL_%=:\n\t"
            "mbarrier.try_wait.parity.acquire.cta.shared::cta.b64 P1, [%0], %1, 0x989680;\n\t"
            "@P1 bra.uni WD_%=;\n\t"
            "bra.uni WL_%=;\n\t"
            "WD_%=:\n\t}"
            :: "r"(mbar), "r"(phase) : "memory");
    }
}

// ---------------------------------------------------------------------------
__global__ void __launch_bounds__(256, 3) fused_kernel(
    const float* __restrict__ mask,
    const float* __restrict__ gt,
    const float* __restrict__ valid,
    float* __restrict__ out) {
    __shared__ ShU sh;
    __shared__ __align__(8) unsigned long long mbar_full[STAGES];
    __shared__ float v1m[NWPB][KK];
    __shared__ float cost[BB][KK][KK];
    __shared__ float mS1M[BB][KK], mSUMM[BB][KK], mSUMG[BB][KK], mV[BB];
    __shared__ int colmap[BB][KK];
    __shared__ float rce[BB * KK], rdice[BB * KK];
    __shared__ int is_last;

    const int b = blockIdx.y;
    const int bx = blockIdx.x;
    const int t = threadIdx.x;
    const int lane = t & 31;
    const int w = t >> 5;
    const unsigned FULL = 0xffffffffu;

    const float* mask_b = mask + (size_t)b * NN * KK;
    const float* gt_b = gt + (size_t)b * NN * KK;
    const float* val_b = valid + (size_t)b * NN;

    const uint32_t sm_m0 = (uint32_t)__cvta_generic_to_shared(&sh.stg.m[0][0]);
    const uint32_t sm_g0 = (uint32_t)__cvta_generic_to_shared(&sh.stg.g[0][0]);
    const uint32_t sm_v0 = (uint32_t)__cvta_generic_to_shared(&sh.stg.v[0][0]);
    const uint32_t mb0 = (uint32_t)__cvta_generic_to_shared(&mbar_full[0]);

    const int nt = (NTILES - bx + GX - 1) / GX;   // rounds for this block

    auto issue = [&](int rr, int s) {
        const int ti = bx + rr * GX;
        const int r0 = ti * TROWS;
        const int np = min(TROWS, NN - r0);
        const uint32_t mB = (uint32_t)(np * 64);
        const uint32_t vB = (uint32_t)(np * 4);
        const uint32_t bar = mb0 + (uint32_t)s * 8;
        mbar_expect_tx(bar, mB * 2 + vB);
        bulk_g2s(sm_m0 + (uint32_t)s * (TROWS * 64), mask_b + (size_t)r0 * KK, mB, bar);
        bulk_g2s(sm_g0 + (uint32_t)s * (TROWS * 64), gt_b + (size_t)r0 * KK, mB, bar);
        bulk_g2s(sm_v0 + (uint32_t)s * (TROWS * 4), val_b + r0, vB, bar);
    };

    if (t == 0) {
#pragma unroll
        for (int s = 0; s < STAGES; s++) mbar_init(mb0 + s * 8, 1);
    }
    __syncthreads();
    if (t == 0) {
        for (int rr = 0; rr < STAGES && rr < nt; rr++) issue(rr, rr);
    }

    // fragment lane geometry
    const int kk4 = lane & 3;    // k offset within chunk (rows +0 / +4)
    const int ilo = lane >> 2;   // i row 0..7 (ihi = +8)
    // accumulators: D jt0/jt1, INTER jt0/jt1 (each 16x8)
    float D0[4] = {0, 0, 0, 0}, D1[4] = {0, 0, 0, 0};
    float I0[4] = {0, 0, 0, 0}, I1[4] = {0, 0, 0, 0};
    float s1lo = 0.0f, s1hi = 0.0f;   // +v*log2(1-m) for i=ilo / i=ilo+8

    for (int r = 0; r < nt; r++) {
        const int s = r & (STAGES - 1);
        const uint32_t ph = (uint32_t)((r >> 2) & 1);
        mbar_wait(mb0 + (uint32_t)s * 8, ph);

        const int np = min(TROWS, NN - (bx + r * GX) * TROWS);
        if (w * 8 < np) {   // tail tile: 32 rows = chunks 0..3 exactly
            const float* M = sh.stg.m[s];
            const float* G = sh.stg.g[s];
            const float* V = sh.stg.v[s];
            const int ka = w * 8 + kk4;      // local row for k = kk4
            const int kb = ka + 4;           // local row for k = kk4+4

            float va = V[ka], vb = V[kb];
            float m0 = M[ka * 16 + ilo];
            float m1 = M[ka * 16 + ilo + 8];
            float m2 = M[kb * 16 + ilo];
            float m3 = M[kb * 16 + ilo + 8];

            float p0 = __log2f(m0), q0 = __log2f(1.0f - m0);
            float p1 = __log2f(m1), q1 = __log2f(1.0f - m1);
            float p2 = __log2f(m2), q2 = __log2f(1.0f - m2);
            float p3 = __log2f(m3), q3 = __log2f(1.0f - m3);

            s1lo = fmaf(va, q0, s1lo); s1hi = fmaf(va, q1, s1hi);
            s1lo = fmaf(vb, q2, s1lo); s1hi = fmaf(vb, q3, s1hi);

            // A fragments (row-major [i=16, k=8])
            uint32_t ad0 = to_tf32(va * (q0 - p0));
            uint32_t ad1 = to_tf32(va * (q1 - p1));
            uint32_t ad2 = to_tf32(vb * (q2 - p2));
            uint32_t ad3 = to_tf32(vb * (q3 - p3));
            uint32_t ar0 = to_tf32(va * m0);
            uint32_t ar1 = to_tf32(va * m1);
            uint32_t ar2 = to_tf32(vb * m2);
            uint32_t ar3 = to_tf32(vb * m3);

            // B fragments (col-major [k=8, j=8]); gt is exact in tf32
            uint32_t b0t0 = __float_as_uint(G[ka * 16 + ilo]);
            uint32_t b1t0 = __float_as_uint(G[kb * 16 + ilo]);
            uint32_t b0t1 = __float_as_uint(G[ka * 16 + ilo + 8]);
            uint32_t b1t1 = __float_as_uint(G[kb * 16 + ilo + 8]);

            mma_tf32(D0[0], D0[1], D0[2], D0[3], ad0, ad1, ad2, ad3, b0t0, b1t0);
            mma_tf32(D1[0], D1[1], D1[2], D1[3], ad0, ad1, ad2, ad3, b0t1, b1t1);
            mma_tf32(I0[0], I0[1], I0[2], I0[3], ar0, ar1, ar2, ar3, b0t0, b1t0);
            mma_tf32(I1[0], I1[1], I1[2], I1[3], ar0, ar1, ar2, ar3, b0t1, b1t1);
        }
        __syncthreads();
        if (t == 0 && r + STAGES < nt) issue(r + STAGES, s);
    }

    // ---- s1m: reduce over the 4 lanes sharing each i ----
    s1lo += __shfl_xor_sync(FULL, s1lo, 1);
    s1lo += __shfl_xor_sync(FULL, s1lo, 2);
    s1hi += __shfl_xor_sync(FULL, s1hi, 1);
    s1hi += __shfl_xor_sync(FULL, s1hi, 2);
    if (kk4 == 0) { v1m[w][ilo] = s1lo; v1m[w][ilo + 8] = s1hi; }
    __syncthreads();   // mainloop fully done before aliasing stage smem

    // ---- fragment writeback -> pti ----
    {
        float* P = sh.epi.pti[w];
        const int jb = kk4 * 2;
        // D (offset 0), INTER (offset 256); jt0 -> j 0..7, jt1 -> j 8..15
        P[ilo * 16 + jb] = D0[0];       P[ilo * 16 + jb + 1] = D0[1];
        P[(ilo + 8) * 16 + jb] = D0[2]; P[(ilo + 8) * 16 + jb + 1] = D0[3];
        P[ilo * 16 + 8 + jb] = D1[0];   P[ilo * 16 + 8 + jb + 1] = D1[1];
        P[(ilo + 8) * 16 + 8 + jb] = D1[2];
        P[(ilo + 8) * 16 + 8 + jb + 1] = D1[3];
        P[256 + ilo * 16 + jb] = I0[0];       P[256 + ilo * 16 + jb + 1] = I0[1];
        P[256 + (ilo + 8) * 16 + jb] = I0[2]; P[256 + (ilo + 8) * 16 + jb + 1] = I0[3];
        P[256 + ilo * 16 + 8 + jb] = I1[0];   P[256 + ilo * 16 + 8 + jb + 1] = I1[1];
        P[256 + (ilo + 8) * 16 + 8 + jb] = I1[2];
        P[256 + (ilo + 8) * 16 + 8 + jb + 1] = I1[3];
    }
    __syncthreads();

    // ---- block reduce -> deterministic per-block partial slot ----
    Part* gp = &g_part[b * GX + bx];
#pragma unroll
    for (int e0 = 0; e0 < 512; e0 += 256) {
        int e = e0 + t;
        float sum = 0.0f;
#pragma unroll
        for (int ww = 0; ww < NWPB; ww++) sum += sh.epi.pti[ww][e];
        gp->e[e] = sum;
    }
    if (t < 16) {
        float sum = 0.0f;
#pragma unroll
        for (int ww = 0; ww < NWPB; ww++) sum += v1m[ww][t];
        gp->e[512 + t] = -sum;   // S1M = -sum(v*log2(1-m))
    }

    __threadfence();
    __syncthreads();
    if (t == 0) {
        int old = atomicAdd(&g_count, 1);
        is_last = (old == NBLK - 1);
    }
    __syncthreads();
    if (!is_last) return;

    if (t == 0) g_count = 0;

    // ---- final reduce: 9 entries per thread, jammed for MLP ----
    {
        float sacc[9];
        const float* bas[9];
        int ok[9];
#pragma unroll
        for (int k = 0; k < 9; k++) {
            int q = t + k * 256;
            ok[k] = (q < NE_TOT);
            sacc[k] = 0.0f;
            if (ok[k]) {
                int bb2 = q / NE_REAL;
                int e = q - bb2 * NE_REAL;
                bas[k] = &g_part[bb2 * GX].e[e];
            } else {
                bas[k] = &g_part[0].e[0];
            }
        }
        for (int gx = 0; gx < GX; gx++) {
#pragma unroll
            for (int k = 0; k < 9; k++)
                if (ok[k]) sacc[k] += bas[k][(size_t)gx * ENT];
        }
#pragma unroll
        for (int k = 0; k < 9; k++) {
            int q = t + k * 256;
            if (ok[k]) sh.epi.facc[q] = sacc[k];
        }
    }
    __syncthreads();

    // ---- marginals from INTER (+ direct S1M) ----
    if (t < BB * KK) {
        int bb2 = t / KK, q = t % KK;
        const float* F = sh.epi.facc + bb2 * NE_REAL;
        float summ = 0.0f, sumg = 0.0f;
#pragma unroll
        for (int x = 0; x < KK; x++) {
            summ += F[256 + q * 16 + x];   // row sum of INTER
            sumg += F[256 + x * 16 + q];   // col sum of INTER
        }
        mS1M[bb2][q] = F[512 + q];
        mSUMM[bb2][q] = summ;
        mSUMG[bb2][q] = sumg;
    }
    __syncthreads();
    if (t < BB) {
        float v = 0.0f;
#pragma unroll
        for (int x = 0; x < KK; x++) v += mSUMG[t][x];
        mV[t] = v;
    }
    __syncthreads();

    // ---- cost matrices ----
    const float LN2 = 0.69314718055994530942f;
    for (int idx = t; idx < BB * 256; idx += 256) {
        int bb2 = idx >> 8;
        int r = idx & 255;
        int ii = r >> 4, jj = r & 15;
        const float* F = sh.epi.facc + bb2 * NE_REAL;
        float denom = fmaxf(mV[bb2], 1.0f);
        float ce = LN2 * (F[ii * 16 + jj] + mS1M[bb2][ii]) / denom;
        float dice = 1.0f - 2.0f * F[256 + ii * 16 + jj] /
                                (mSUMM[bb2][ii] + mSUMG[bb2][jj] + EPSF);
        cost[bb2][ii][jj] = W_CE * ce + W_DICE * dice;
    }
    __syncthreads();

    // ---- warp-parallel Hungarian (JV), one warp per batch ----
    if (w < BB) {
        const int bb2 = w;
        float ur = 0.0f;
        float vv = 0.0f;
        int pcol = 0;

        for (int ii = 1; ii <= KK; ii++) {
            if (lane == 0) pcol = ii;
            float minv = 1e30f;
            int way = 0;
            int used = 0;
            int rowcov = 0;
            int j0 = 0;

            while (true) {
                if (lane == j0) used = 1;
                int i0 = __shfl_sync(FULL, pcol, j0);
                if (lane == i0) rowcov = 1;
                float u_i0 = __shfl_sync(FULL, ur, i0);

                int active = (lane >= 1 && lane <= KK && !used);
                if (active) {
                    float c = cost[bb2][i0 - 1][lane - 1];
                    float cur = c - u_i0 - vv;
                    if (cur < minv) { minv = cur; way = j0; }
                }
                float val = active ? minv : 1e30f;
                float red = val;
#pragma unroll
                for (int off = 16; off; off >>= 1)
                    red = fminf(red, __shfl_xor_sync(FULL, red, off));
                unsigned bal = __ballot_sync(FULL, val == red);
                int j1 = __ffs(bal) - 1;
                float delta = red;

                if (rowcov) ur += delta;
                if (used) vv -= delta;
                else if (lane >= 1 && lane <= KK) minv -= delta;

                j0 = j1;
                int pj = __shfl_sync(FULL, pcol, j0);
                if (pj == 0) break;
            }
            while (j0 != 0) {
                int j1 = __shfl_sync(FULL, way, j0);
                int pv = __shfl_sync(FULL, pcol, j1);
                if (lane == j0) pcol = pv;
                j0 = j1;
            }
        }
        if (lane >= 1 && lane <= KK) colmap[bb2][pcol - 1] = lane - 1;
    }
    __syncthreads();

    // ---- loss ----
    if (t < BB * KK) {
        int bb2 = t / KK, ii = t % KK;
        int jj = colmap[bb2][ii];
        const float* F = sh.epi.facc + bb2 * NE_REAL;
        rce[t] = LN2 * (F[ii * 16 + jj] + mS1M[bb2][ii]);
        rdice[t] = 1.0f - 2.0f * F[256 + ii * 16 + jj] /
                              (mSUMM[bb2][ii] + mSUMG[bb2][jj] + EPSF);
    }
    __syncthreads();

    if (t == 0) {
        float cs = 0.0f, ds = 0.0f, vt = 0.0f;
        for (int x = 0; x < BB * KK; x++) { cs += rce[x]; ds += rdice[x]; }
        for (int bb2 = 0; bb2 < BB; bb2++) vt += mV[bb2];
        float l_ce = cs / (fmaxf(vt, 1.0f) * (float)KK);
        float l_dice = ds / (float)(BB * KK);
        out[0] = W_CE * l_ce + W_DICE * l_dice;
    }
}

// ---------------------------------------------------------------------------
extern "C" void kernel_launch(void* const* d_in, const int* in_sizes, int n_in,
                              void* d_out, int out_size) {
    const float* mask = (const float*)d_in[0];
    const float* gt = (const float*)d_in[1];
    const float* valid = (const float*)d_in[2];
    float* out = (float*)d_out;

    dim3 grid(GX, BB);
    fused_kernel<<<grid, 256>>>(mask, gt, valid, out);
}